// round 9
// baseline (speedup 1.0000x reference)
#include <cuda_runtime.h>
#include <cuda_fp16.h>

// InterpolateSparse2d on GB300 — round 8: tile-binned gather, smem scratch.
// R3 (105us) round-trips 157MB of fp16 scratch through DRAM. R4-R7 fused
// variants all lost to sync starvation. v5 removes the DRAM scratch entirely:
// bin points by (batch, 64x10 tile); one block per tile loads tile+halo
// (65x11 px x 64ch) fp32->fp16 into SMEM (conflict-free stride-33-word
// layout), then gathers its ~167 points from smem. x read once (~1.24x halo/
// sector amp), out written once. No inter-block sync anywhere.

#define BB 16
#define CC 64
#define HX 240
#define WX 320
#define NN 20000
#define HW (HX * WX)
#define NPTS (BB * NN)

#define TW 64
#define TH 10
#define NTX 5                    // 320/64
#define NTY 24                   // 240/10
#define TPB (NTX * NTY)          // 120 tiles per batch
#define TILES (BB * TPB)         // 1920

#define HALO_W 65
#define HALO_H 11
#define SPIX (HALO_W * HALO_H)   // 715 pixels
#define SSTRIDE 66               // halves per pixel slot (33 words: odd mod 32
                                 // -> conflict-free channel-major stores)
#define SMEM_BYTES (SPIX * SSTRIDE * 2)   // 94,380 B

__device__ int g_cnt[TILES];
__device__ int g_off[TILES + 1];
__device__ int g_cur[TILES];
__device__ int g_order[NPTS];

// ---------------------------------------------------------------------------
__device__ __forceinline__ int point_tile(const float* __restrict__ pos,
                                          int pn, float Wf, float Hf,
                                          int* px0, int* py0)
{
    float px = pos[pn * 2 + 0] * (float)(WX - 1) / Wf;
    float py = pos[pn * 2 + 1] * (float)(HX - 1) / Hf;
    int x0 = min(max((int)floorf(px), 0), WX - 1);
    int y0 = min(max((int)floorf(py), 0), HX - 1);
    *px0 = x0; *py0 = y0;
    int b = pn / NN;
    return b * TPB + (y0 / TH) * NTX + (x0 >> 6);
}

__global__ void k_init()
{
    int i = blockIdx.x * blockDim.x + threadIdx.x;
    if (i < TILES) g_cnt[i] = 0;
}

__global__ void k_count(const float* __restrict__ pos,
                        const int* __restrict__ Hp, const int* __restrict__ Wp)
{
    int pn = blockIdx.x * blockDim.x + threadIdx.x;
    if (pn >= NPTS) return;
    int x0, y0;
    int t = point_tile(pos, pn, (float)(*Wp), (float)(*Hp), &x0, &y0);
    atomicAdd(&g_cnt[t], 1);
}

__global__ void __launch_bounds__(1024) k_scan()
{
    __shared__ int s[2048];
    int tid = threadIdx.x;
    s[tid]        = (tid < TILES) ? g_cnt[tid] : 0;
    s[tid + 1024] = (tid + 1024 < TILES) ? g_cnt[tid + 1024] : 0;
    __syncthreads();
    for (int off = 1; off < 2048; off <<= 1) {
        int a0 = (tid >= off) ? s[tid - off] : 0;
        int a1 = s[tid + 1024 - off];          // tid+1024 >= off always
        __syncthreads();
        s[tid] += a0;
        s[tid + 1024] += a1;
        __syncthreads();
    }
    if (tid == 0) g_off[0] = 0;
    if (tid < TILES) {
        g_off[tid + 1] = s[tid];
        g_cur[tid] = tid ? s[tid - 1] : 0;
    }
    int j = tid + 1024;
    if (j < TILES) {
        g_off[j + 1] = s[j];
        g_cur[j] = s[j - 1];
    }
}

__global__ void k_scatter(const float* __restrict__ pos,
                          const int* __restrict__ Hp, const int* __restrict__ Wp)
{
    int pn = blockIdx.x * blockDim.x + threadIdx.x;
    if (pn >= NPTS) return;
    int x0, y0;
    int t = point_tile(pos, pn, (float)(*Wp), (float)(*Hp), &x0, &y0);
    int slot = atomicAdd(&g_cur[t], 1);
    g_order[slot] = pn;
}

// ---------------------------------------------------------------------------
extern __shared__ __half s_tile[];   // [pix][ch] halves, stride SSTRIDE

__global__ void __launch_bounds__(256)
k_tile_gather(const float* __restrict__ x,
              const float* __restrict__ pos,
              const int* __restrict__ Hp, const int* __restrict__ Wp,
              float* __restrict__ out)
{
    const int t   = blockIdx.x;
    const int b   = t / TPB;
    const int tt  = t - b * TPB;
    const int ty  = tt / NTX;
    const int tx  = tt - ty * NTX;
    const int gx0 = tx * TW;
    const int gy0 = ty * TH;
    const int tid = threadIdx.x;

    // ---- phase 1: load tile+halo, 64ch x 11 x 65, fp32 -> fp16 smem ----
    // Consecutive threads -> consecutive xx: global 128B-coalesced reads;
    // smem stores stride 33 words (odd mod 32) -> conflict-free.
    const float* xb = x + (long long)b * CC * HW;
    for (int idx = tid; idx < CC * HALO_H * HALO_W; idx += 256) {
        int xx = idx % HALO_W;
        int r  = idx / HALO_W;
        int y  = r % HALO_H;
        int c  = r / HALO_H;
        int gx = min(gx0 + xx, WX - 1);
        int gy = min(gy0 + y,  HX - 1);
        float v = __ldg(xb + c * HW + gy * WX + gx);
        s_tile[(y * HALO_W + xx) * SSTRIDE + c] = __float2half_rn(v);
    }
    __syncthreads();

    // ---- phase 2: gather this tile's points from smem ----
    const float Wf = (float)(*Wp);
    const float Hf = (float)(*Hp);
    const int start = g_off[t];
    const int end   = g_off[t + 1];
    const int l8 = tid & 7;                  // 8 channels per lane
    const unsigned* s32 = (const unsigned*)s_tile;

    for (int slot = start + (tid >> 3); slot < end; slot += 32) {
        int pn = g_order[slot];

        float px = __ldg(pos + pn * 2 + 0) * (float)(WX - 1) / Wf;
        float py = __ldg(pos + pn * 2 + 1) * (float)(HX - 1) / Hf;

        int x0 = min(max((int)floorf(px), 0), WX - 1);
        int y0 = min(max((int)floorf(py), 0), HX - 1);
        int x1 = min(x0 + 1, WX - 1);
        int y1 = min(y0 + 1, HX - 1);

        float x0f = (float)x0, x1f = (float)x1;
        float y0f = (float)y0, y1f = (float)y1;

        float wa = (x1f - px) * (y1f - py);
        float wb = (x1f - px) * (py - y0f);
        float wc = (px - x0f) * (y1f - py);
        float wd = (px - x0f) * (py - y0f);

        int lx0 = x0 - gx0, lx1 = x1 - gx0;
        int ly0 = y0 - gy0, ly1 = y1 - gy0;

        int p00 = (ly0 * HALO_W + lx0) * 33 + l8 * 4;   // word index
        int p01 = (ly0 * HALO_W + lx1) * 33 + l8 * 4;
        int p10 = (ly1 * HALO_W + lx0) * 33 + l8 * 4;
        int p11 = (ly1 * HALO_W + lx1) * 33 + l8 * 4;

        float r[8];
        #pragma unroll
        for (int w = 0; w < 4; w++) {
            float2 fa = __half22float2(*(const __half2*)&s32[p00 + w]);
            float2 fb = __half22float2(*(const __half2*)&s32[p10 + w]);
            float2 fc = __half22float2(*(const __half2*)&s32[p01 + w]);
            float2 fd = __half22float2(*(const __half2*)&s32[p11 + w]);
            r[2 * w + 0] = wa * fa.x + wb * fb.x + wc * fc.x + wd * fd.x;
            r[2 * w + 1] = wa * fa.y + wb * fb.y + wc * fc.y + wd * fd.y;
        }

        float4* o = (float4*)out;
        long long ob = (long long)pn * 16 + l8 * 2;
        __stcs(o + ob + 0, make_float4(r[0], r[1], r[2], r[3]));
        __stcs(o + ob + 1, make_float4(r[4], r[5], r[6], r[7]));
    }
}

// ---------------------------------------------------------------------------
extern "C" void kernel_launch(void* const* d_in, const int* in_sizes, int n_in,
                              void* d_out, int out_size)
{
    const float* x   = (const float*)d_in[0];
    const float* pos = (const float*)d_in[1];
    const int*   Hp  = (const int*)d_in[2];
    const int*   Wp  = (const int*)d_in[3];
    float* out = (float*)d_out;

    // Function attribute (not an allocation; immediate, idempotent — set on
    // the pre-capture correctness call and every call thereafter).
    cudaFuncSetAttribute(k_tile_gather,
                         cudaFuncAttributeMaxDynamicSharedMemorySize,
                         SMEM_BYTES);

    k_init   <<<(TILES + 255) / 256, 256>>>();
    k_count  <<<(NPTS + 255) / 256, 256>>>(pos, Hp, Wp);
    k_scan   <<<1, 1024>>>();
    k_scatter<<<(NPTS + 255) / 256, 256>>>(pos, Hp, Wp);
    k_tile_gather<<<TILES, 256, SMEM_BYTES>>>(x, pos, Hp, Wp, out);
}

// round 10
// speedup vs baseline: 2.2620x; 2.2620x over previous
#include <cuda_runtime.h>
#include <cuda_fp16.h>

// InterpolateSparse2d on GB300 — round 9: split-grid v2, fence-free.
// R7's split-grid lost to a specific bug: __threadfence() by ALL 256 threads
// per transpose chunk = ~10M CCTL.IVALL L1-flushes (self- and neighbor-
// thrashing). v2 replaces every fence with the proper hb chain:
//   producer: STGs -> __syncthreads (hb) -> 1 thread red.release.gpu
//   consumer: 1 thread ld.acquire.gpu poll -> __syncthreads (hb)
// Stale-L1 is impossible by construction: scratch is full-size write-once, so
// no consumer reads a scratch address before its release is observed.
// 592 persistent producer blocks stream transpose NCHW fp32 -> NHWC fp16;
// 296 consumer blocks trail by ~1 batch doing the gather from hot L2.

#define BB 16
#define CC 64
#define HX 240
#define WX 320
#define NN 20000
#define HW (HX * WX)

#define CH_T 2400                    // transpose chunks per batch (32 px each)
#define CH_G 625                     // gather chunks per batch (32 pts each)

#define T_BLOCKS 592
#define G_BLOCKS 296
#define GRID_BLOCKS (T_BLOCKS + G_BLOCKS)   // 888 = 148 SM * 6, all resident

// Full scratch [B][H][W][64ch fp16] = 157MB, written exactly once per launch.
__device__ uint4 g_scr[(long long)BB * HW * 8];
__device__ int g_tdone[BB];          // transpose chunks completed per batch

__global__ void init_counters()
{
    int t = threadIdx.x;
    if (t < BB) g_tdone[t] = 0;
}

__global__ void __launch_bounds__(256, 6)
fused_interp5(const float* __restrict__ x,
              const float* __restrict__ pos,
              const int* __restrict__ Hp,
              const int* __restrict__ Wp,
              float* __restrict__ out)
{
    const int tid = threadIdx.x;

    if (blockIdx.x < T_BLOCKS) {
        // ================= producer: transpose NCHW fp32 -> NHWC fp16 =======
        __shared__ float tile[64 * 33];

        for (int ch = blockIdx.x; ch < BB * CH_T; ch += T_BLOCKS) {
            int b  = ch / CH_T;
            int p0 = (ch - b * CH_T) * 32;

            int pl = tid & 31;             // pixel lane
            int c0 = tid >> 5;             // 0..7

            const float* src = x + (long long)b * CC * HW + p0;
            #pragma unroll
            for (int i = 0; i < 8; i++) {
                int c = c0 + i * 8;
                // evict-first: x is single-use; don't evict hot scratch in L2.
                tile[c * 33 + pl] = __ldcs(src + (long long)c * HW + pl);
            }
            __syncthreads();

            int c2 = tid & 31;             // half2 index (channels 2c2,2c2+1)
            int pg = tid >> 5;             // 0..7
            __half2* dst = (__half2*)(g_scr + ((long long)b * HW + p0) * 8);
            #pragma unroll
            for (int i = 0; i < 4; i++) {
                int p = pg + i * 8;
                float lo = tile[(2 * c2)     * 33 + p];
                float hi = tile[(2 * c2 + 1) * 33 + p];
                dst[p * 32 + c2] = __floats2half2_rn(lo, hi);
            }

            // hb: all threads' STGs -> barrier -> single release-reduction.
            // No membar/CCTL anywhere.
            __syncthreads();
            if (tid == 0) {
                asm volatile("red.release.gpu.global.add.s32 [%0], %1;"
                             :: "l"(&g_tdone[b]), "r"(1) : "memory");
            }
        }
    } else {
        // ================= consumer: bilinear gather from fp16 NHWC =========
        const float Wf = (float)(*Wp);
        const float Hf = (float)(*Hp);
        __shared__ int s_ready;            // highest batch known complete + 1

        if (tid == 0) s_ready = 0;
        __syncthreads();

        int gid = blockIdx.x - T_BLOCKS;
        for (int g = gid; g < BB * CH_G; g += G_BLOCKS) {
            int b = g / CH_G;

            // One acquire-poll per batch transition.
            if (s_ready <= b) {
                if (tid == 0) {
                    int v;
                    do {
                        __nanosleep(128);
                        asm volatile("ld.acquire.gpu.global.s32 %0, [%1];"
                                     : "=r"(v) : "l"(&g_tdone[b]) : "memory");
                    } while (v < CH_T);
                    s_ready = b + 1;
                }
                __syncthreads();           // hb: acquire propagates to block
            }

            int chunk = g - b * CH_G;
            int lane8 = tid & 7;           // 8 channels per lane
            int p     = chunk * 32 + (tid >> 3);
            long long pn = (long long)b * NN + p;

            float posx = pos[pn * 2 + 0];
            float posy = pos[pn * 2 + 1];

            float px = posx * (float)(WX - 1) / Wf;
            float py = posy * (float)(HX - 1) / Hf;

            int x0 = (int)floorf(px);
            int y0 = (int)floorf(py);
            x0 = min(max(x0, 0), WX - 1);
            y0 = min(max(y0, 0), HX - 1);
            int x1 = min(x0 + 1, WX - 1);
            int y1 = min(y0 + 1, HX - 1);

            float x0f = (float)x0, x1f = (float)x1;
            float y0f = (float)y0, y1f = (float)y1;

            float wa = (x1f - px) * (y1f - py);
            float wb = (x1f - px) * (py - y0f);
            float wc = (px - x0f) * (y1f - py);
            float wd = (px - x0f) * (py - y0f);

            long long bufb = (long long)b * HW;
            long long i00 = (bufb + y0 * WX + x0) * 8 + lane8;
            long long i01 = (bufb + y0 * WX + x1) * 8 + lane8;
            long long i10 = (bufb + y1 * WX + x0) * 8 + lane8;
            long long i11 = (bufb + y1 * WX + x1) * 8 + lane8;

            uint4 A  = __ldg(g_scr + i00);
            uint4 Bv = __ldg(g_scr + i10);
            uint4 Cv = __ldg(g_scr + i01);
            uint4 D  = __ldg(g_scr + i11);

            float r[8];
            const unsigned* au = (const unsigned*)&A;
            const unsigned* bu = (const unsigned*)&Bv;
            const unsigned* cu = (const unsigned*)&Cv;
            const unsigned* du = (const unsigned*)&D;
            #pragma unroll
            for (int j = 0; j < 4; j++) {
                float2 fa = __half22float2(*(const __half2*)&au[j]);
                float2 fb = __half22float2(*(const __half2*)&bu[j]);
                float2 fc = __half22float2(*(const __half2*)&cu[j]);
                float2 fd = __half22float2(*(const __half2*)&du[j]);
                r[2 * j + 0] = wa * fa.x + wb * fb.x + wc * fc.x + wd * fd.x;
                r[2 * j + 1] = wa * fa.y + wb * fb.y + wc * fc.y + wd * fd.y;
            }

            // evict-first store: out is write-once.
            float4* o = (float4*)out;
            long long ob = pn * 16 + lane8 * 2;
            __stcs(o + ob + 0, make_float4(r[0], r[1], r[2], r[3]));
            __stcs(o + ob + 1, make_float4(r[4], r[5], r[6], r[7]));
        }
    }
}

extern "C" void kernel_launch(void* const* d_in, const int* in_sizes, int n_in,
                              void* d_out, int out_size)
{
    const float* x   = (const float*)d_in[0];
    const float* pos = (const float*)d_in[1];
    const int*   Hp  = (const int*)d_in[2];
    const int*   Wp  = (const int*)d_in[3];
    float* out = (float*)d_out;

    init_counters<<<1, 32>>>();
    fused_interp5<<<GRID_BLOCKS, 256>>>(x, pos, Hp, Wp, out);
}

// round 11
// speedup vs baseline: 2.9550x; 1.3064x over previous
#include <cuda_runtime.h>
#include <cuda_fp16.h>

// InterpolateSparse2d on GB300 — round 10: R3 two-kernel structure + polish.
// Fusion (R4-R9, five variants) conclusively loses to bulk-synchronous kernels
// that each saturate the chip. R3 baseline: transpose 75us + gather 30us.
// Polish: (1) __ldcs on single-use x stream; (2) gather walks batches in
// REVERSE order — L2 holds the last-written ~100MB of the 157MB scratch at
// transpose end, so starting from batch 15 converts scratch DRAM reads to L2
// hits; (3) __stcs on write-once out.

#define BB 16
#define CC 64
#define HX 240
#define WX 320
#define NN 20000
#define HW (HX * WX)

// Scratch: [B][H][W][64 ch fp16] = 157,286,400 bytes.
__device__ uint4 g_xt[(long long)BB * HW * 8];   // 8 uint4 = 64 halves per pixel

// ---------------------------------------------------------------------------
// Kernel 1: transpose [B,C,H,W] fp32 -> [B,H,W,C] fp16.
// Block = 256 threads handles 32 pixels x 64 channels of one batch.
// ---------------------------------------------------------------------------
__global__ void __launch_bounds__(256)
transpose_nchw_to_nhwc_h(const float* __restrict__ x)
{
    __shared__ float tile[64 * 33];   // [c][pixel], stride 33: conflict-free

    int blk = blockIdx.x;                  // b * (HW/32) + pixel_chunk
    int b   = blk / (HW / 32);
    int p0  = (blk % (HW / 32)) * 32;

    int t  = threadIdx.x;
    int pl = t & 31;          // pixel lane 0..31
    int c0 = t >> 5;          // 0..7

    const float* src = x + (long long)b * CC * HW + p0;
    #pragma unroll
    for (int i = 0; i < 8; i++) {
        int c = c0 + i * 8;
        // evict-first: x is single-use; preserve L2 for the scratch.
        tile[c * 33 + pl] = __ldcs(src + (long long)c * HW + pl);
    }
    __syncthreads();

    // Write phase: thread -> (channel-pair c2, pixel group pg).
    int c2 = t & 31;          // half2 index: channels 2*c2, 2*c2+1
    int pg = t >> 5;          // 0..7
    __half2* dst = (__half2*)(g_xt + ((long long)b * HW + p0) * 8);
    #pragma unroll
    for (int i = 0; i < 4; i++) {
        int p = pg + i * 8;
        float lo = tile[(2 * c2)     * 33 + p];
        float hi = tile[(2 * c2 + 1) * 33 + p];
        dst[p * 32 + c2] = __floats2half2_rn(lo, hi);
    }
}

// ---------------------------------------------------------------------------
// Kernel 2: bilinear gather from fp16 [B,H,W,C], batches in REVERSE order.
// 8 threads per point; each thread owns 8 channels (one uint4 per corner).
// ---------------------------------------------------------------------------
__global__ void __launch_bounds__(256)
gather_bilinear_h(const float* __restrict__ pos,
                  const int* __restrict__ Hp,
                  const int* __restrict__ Wp,
                  float* __restrict__ out)
{
    // Reverse point-group mapping: early blocks process the LAST-transposed
    // batches, whose scratch is still resident in L2.
    int grp_fwd = blockIdx.x * (blockDim.x >> 3) + (threadIdx.x >> 3); // 32-pt? no: point group = one point per 8 lanes
    // grp_fwd indexes points directly (each point uses 8 threads).
    int pn_fwd = grp_fwd;
    if (pn_fwd >= BB * NN) return;
    int pn = BB * NN - 1 - pn_fwd;          // reversed: batch 15 first
    int lane8 = threadIdx.x & 7;            // 8 channels per lane
    int b = pn / NN;

    float posx = pos[pn * 2 + 0];
    float posy = pos[pn * 2 + 1];

    float Wf = (float)(*Wp);
    float Hf = (float)(*Hp);

    // Match reference arithmetic order: pos * (Wx-1) / W
    float px = posx * (float)(WX - 1) / Wf;
    float py = posy * (float)(HX - 1) / Hf;

    int x0 = (int)floorf(px);
    int y0 = (int)floorf(py);
    x0 = min(max(x0, 0), WX - 1);
    y0 = min(max(y0, 0), HX - 1);
    int x1 = min(x0 + 1, WX - 1);
    int y1 = min(y0 + 1, HX - 1);

    float x0f = (float)x0, x1f = (float)x1;
    float y0f = (float)y0, y1f = (float)y1;

    float wa = (x1f - px) * (y1f - py);   // (y0,x0)
    float wb = (x1f - px) * (py - y0f);   // (y1,x0)
    float wc = (px - x0f) * (y1f - py);   // (y0,x1)
    float wd = (px - x0f) * (py - y0f);   // (y1,x1)

    long long rowb = (long long)b * HX;
    long long i00 = ((rowb + y0) * WX + x0) * 8 + lane8;
    long long i01 = ((rowb + y0) * WX + x1) * 8 + lane8;
    long long i10 = ((rowb + y1) * WX + x0) * 8 + lane8;
    long long i11 = ((rowb + y1) * WX + x1) * 8 + lane8;

    // 4 independent 16B gathers (MLP=4 per thread, 32 per point).
    uint4 A  = __ldg(g_xt + i00);
    uint4 Bv = __ldg(g_xt + i10);
    uint4 Cv = __ldg(g_xt + i01);
    uint4 D  = __ldg(g_xt + i11);

    float r[8];
    const unsigned* au = (const unsigned*)&A;
    const unsigned* bu = (const unsigned*)&Bv;
    const unsigned* cu = (const unsigned*)&Cv;
    const unsigned* du = (const unsigned*)&D;
    #pragma unroll
    for (int j = 0; j < 4; j++) {
        float2 fa = __half22float2(*(const __half2*)&au[j]);
        float2 fb = __half22float2(*(const __half2*)&bu[j]);
        float2 fc = __half22float2(*(const __half2*)&cu[j]);
        float2 fd = __half22float2(*(const __half2*)&du[j]);
        r[2 * j + 0] = wa * fa.x + wb * fb.x + wc * fc.x + wd * fd.x;
        r[2 * j + 1] = wa * fa.y + wb * fb.y + wc * fc.y + wd * fd.y;
    }

    // Write-once output: evict-first. Within a warp: 4 consecutive (reversed)
    // points x 8 lanes -> two 128B segments per point, still fully coalesced.
    float4* o = (float4*)out;
    long long ob = (long long)pn * 16 + lane8 * 2;
    __stcs(o + ob + 0, make_float4(r[0], r[1], r[2], r[3]));
    __stcs(o + ob + 1, make_float4(r[4], r[5], r[6], r[7]));
}

extern "C" void kernel_launch(void* const* d_in, const int* in_sizes, int n_in,
                              void* d_out, int out_size)
{
    const float* x   = (const float*)d_in[0];
    const float* pos = (const float*)d_in[1];
    const int*   Hp  = (const int*)d_in[2];
    const int*   Wp  = (const int*)d_in[3];
    float* out = (float*)d_out;

    // Kernel 1: transpose+downconvert. 16 batches * 2400 pixel-chunks.
    transpose_nchw_to_nhwc_h<<<BB * (HW / 32), 256>>>(x);

    // Kernel 2: gather. 320000 points * 8 threads / 256.
    const int total = BB * NN * 8;
    gather_bilinear_h<<<(total + 255) / 256, 256>>>(pos, Hp, Wp, out);
}